// round 15
// baseline (speedup 1.0000x reference)
#include <cuda_runtime.h>
#include <cuda_bf16.h>
#include <math.h>

#define NPTS 65536
#define KNB  16
#define EPSB 1e-5f
#define PI_F 3.14159265358979f

typedef unsigned long long ull;

__device__ float g_q[NPTS * 64];
__device__ float g_k[NPTS * 64];
__device__ float g_v[NPTS * 64];
__device__ float g_gate[NPTS * 8];
__device__ float g_segmax[4 * 64];

// ---- packed f32x2 helpers ----
__device__ __forceinline__ void ffma2(ull& d, ull a, ull b) {
    asm("fma.rn.f32x2 %0, %1, %2, %0;" : "+l"(d) : "l"(a), "l"(b));
}
__device__ __forceinline__ ull ffma2_3(ull a, ull b, ull c) {
    ull d; asm("fma.rn.f32x2 %0, %1, %2, %3;" : "=l"(d) : "l"(a), "l"(b), "l"(c)); return d;
}
__device__ __forceinline__ ull dupf(float x) {
    ull r; asm("mov.b64 %0, {%1, %1};" : "=l"(r) : "f"(x)); return r;
}
__device__ __forceinline__ float2 unpk(ull v) {
    float2 r; asm("mov.b64 {%0, %1}, %2;" : "=f"(r.x), "=f"(r.y) : "l"(v)); return r;
}

// ---------------- Kernel 0: zero segmax ----------------
__global__ void segmax_init_kernel() { g_segmax[threadIdx.x] = 0.f; }

// ---------------- Kernel 1: fused q,k,v projections + segment max ----------------
// 256 threads, 64 rows/block. Thread = (cp = t&31 -> channels 2cp,2cp+1; rg = t>>5 -> 8 rows).
// Packed f32x2 accumulation: 24 FFMA2 + 8 LDS + 3 LDG.64 per j (vs 48 FFMA + 16 LDS before).
// Segment-max fused: per-thread atomicMax of relu'd q per (segment, channel).
__global__ __launch_bounds__(256) void qkv_kernel(
    const float* __restrict__ feat,
    const float* __restrict__ Wq, const float* __restrict__ bq, const float* __restrict__ bnq,
    const float* __restrict__ Wk, const float* __restrict__ bk, const float* __restrict__ bnk,
    const float* __restrict__ Wv, const float* __restrict__ bv,
    const int* __restrict__ offset)
{
    __shared__ float sf[64 * 64];
    __shared__ int offs[4];
    int t = threadIdx.x;
    int row0 = blockIdx.x * 64;
    if (t < 4) offs[t] = offset[t];
    for (int i = t; i < 64 * 64; i += 256) sf[i] = feat[row0 * 64 + i];
    __syncthreads();

    int cp = t & 31, rg = t >> 5;
    int c0 = cp * 2;
    ull aq[8], ak[8], av[8];
#pragma unroll
    for (int r = 0; r < 8; r++) { aq[r] = 0ULL; ak[r] = 0ULL; av[r] = 0ULL; }

#pragma unroll 4
    for (int j = 0; j < 64; j++) {
        ull wq2 = *(const ull*)&Wq[j * 64 + c0];
        ull wk2 = *(const ull*)&Wk[j * 64 + c0];
        ull wv2 = *(const ull*)&Wv[j * 64 + c0];
        const float* fr = &sf[(rg * 8) * 64 + j];
#pragma unroll
        for (int r = 0; r < 8; r++) {
            ull f2 = dupf(fr[r * 64]);
            ffma2(aq[r], f2, wq2);
            ffma2(ak[r], f2, wk2);
            ffma2(av[r], f2, wv2);
        }
    }

    // bn fold for both channels
    float sq0  = bnq[c0] * rsqrtf(bnq[192 + c0] + EPSB);
    float sq1  = bnq[c0 + 1] * rsqrtf(bnq[192 + c0 + 1] + EPSB);
    float shq0 = bnq[64 + c0] + (bq[c0] - bnq[128 + c0]) * sq0;
    float shq1 = bnq[64 + c0 + 1] + (bq[c0 + 1] - bnq[128 + c0 + 1]) * sq1;
    float sk0  = bnk[c0] * rsqrtf(bnk[192 + c0] + EPSB);
    float sk1  = bnk[c0 + 1] * rsqrtf(bnk[192 + c0 + 1] + EPSB);
    float shk0 = bnk[64 + c0] + (bk[c0] - bnk[128 + c0]) * sk0;
    float shk1 = bnk[64 + c0 + 1] + (bk[c0 + 1] - bnk[128 + c0 + 1]) * sk1;
    float bv0 = bv[c0], bv1 = bv[c0 + 1];

    // store + fused segment-max tracking (q >= 0 so atomicMax-int trick is valid)
    int curseg = -1;
    float m0 = 0.f, m1 = 0.f;
#pragma unroll
    for (int r = 0; r < 8; r++) {
        int row = row0 + rg * 8 + r;
        float2 q2 = unpk(aq[r]);
        float2 k2 = unpk(ak[r]);
        float2 v2 = unpk(av[r]);
        float q0 = fmaxf(q2.x * sq0 + shq0, 0.f);
        float q1 = fmaxf(q2.y * sq1 + shq1, 0.f);
        *(float2*)&g_q[row * 64 + c0] = make_float2(q0, q1);
        *(float2*)&g_k[row * 64 + c0] = make_float2(fmaxf(k2.x * sk0 + shk0, 0.f),
                                                    fmaxf(k2.y * sk1 + shk1, 0.f));
        *(float2*)&g_v[row * 64 + c0] = make_float2(v2.x + bv0, v2.y + bv1);
        int s = 0;
#pragma unroll
        for (int jj = 0; jj < 4; jj++) s += (offs[jj] <= row) ? 1 : 0;
        if (s != curseg) {
            if (curseg >= 0) {
                atomicMax((int*)&g_segmax[curseg * 64 + c0], __float_as_int(m0));
                atomicMax((int*)&g_segmax[curseg * 64 + c0 + 1], __float_as_int(m1));
            }
            curseg = s; m0 = 0.f; m1 = 0.f;
        }
        m0 = fmaxf(m0, q0); m1 = fmaxf(m1, q1);
    }
    atomicMax((int*)&g_segmax[curseg * 64 + c0], __float_as_int(m0));
    atomicMax((int*)&g_segmax[curseg * 64 + c0 + 1], __float_as_int(m1));
}

// ---------------- Kernel 3: gate MLP, 32 rows per block, 256 threads ----------------
struct alignas(16) GateSmem {
    float sW1h[96 * 64];
    float gin[32 * 192];
    float sW2[64 * 8];
    float s_sc[64], s_sh[64], s_b2[8];
    int   offs[4];
    int   sidx[32 * 16];
};

__global__ __launch_bounds__(256, 4) void gate_kernel(
    const int* __restrict__ ridx, const int* __restrict__ offset,
    const float* __restrict__ cgW1, const float* __restrict__ cgb1,
    const float* __restrict__ cgbn, const float* __restrict__ cgW2,
    const float* __restrict__ cgb2)
{
    extern __shared__ char graw[];
    GateSmem& S = *reinterpret_cast<GateSmem*>(graw);
    float* sW1h = S.sW1h;
    float* gin  = S.gin;
    float* sW2  = S.sW2;
    int t = threadIdx.x;
    int n0 = blockIdx.x * 32;
    for (int i = t; i < 64 * 8; i += 256) sW2[i] = cgW2[i];
    if (t < 64) {
        float sc = cgbn[t] * rsqrtf(cgbn[192 + t] + EPSB);
        S.s_sc[t] = sc;
        S.s_sh[t] = cgbn[64 + t] + (cgb1[t] - cgbn[128 + t]) * sc;
    }
    if (t < 8) S.s_b2[t] = cgb2[t];
    if (t < 4) S.offs[t] = offset[t];
    for (int i = t; i < 512; i += 256) {
        int raw = ridx[n0 * KNB + i];
        S.sidx[i] = raw < 0 ? 0 : raw;
    }
    __syncthreads();
    {
        int c8 = (t & 7) * 8;
        int r = t >> 3;
        int n = n0 + r;
        float4 qa = *(const float4*)&g_q[n * 64 + c8];
        float4 qb = *(const float4*)&g_q[n * 64 + c8 + 4];
        float4 ma0 = make_float4(0.f,0.f,0.f,0.f), ma1 = ma0;
        float4 mb0 = ma0, mb1 = ma0;
#pragma unroll
        for (int k = 0; k < KNB; k += 2) {
            int id0 = S.sidx[r * KNB + k];
            int id1 = S.sidx[r * KNB + k + 1];
            float4 va0 = *(const float4*)&g_q[id0 * 64 + c8];
            float4 vb0 = *(const float4*)&g_q[id0 * 64 + c8 + 4];
            float4 va1 = *(const float4*)&g_q[id1 * 64 + c8];
            float4 vb1 = *(const float4*)&g_q[id1 * 64 + c8 + 4];
            ma0.x = fmaxf(ma0.x, va0.x); ma0.y = fmaxf(ma0.y, va0.y);
            ma0.z = fmaxf(ma0.z, va0.z); ma0.w = fmaxf(ma0.w, va0.w);
            mb0.x = fmaxf(mb0.x, vb0.x); mb0.y = fmaxf(mb0.y, vb0.y);
            mb0.z = fmaxf(mb0.z, vb0.z); mb0.w = fmaxf(mb0.w, vb0.w);
            ma1.x = fmaxf(ma1.x, va1.x); ma1.y = fmaxf(ma1.y, va1.y);
            ma1.z = fmaxf(ma1.z, va1.z); ma1.w = fmaxf(ma1.w, va1.w);
            mb1.x = fmaxf(mb1.x, vb1.x); mb1.y = fmaxf(mb1.y, vb1.y);
            mb1.z = fmaxf(mb1.z, vb1.z); mb1.w = fmaxf(mb1.w, vb1.w);
        }
        float4 ma = make_float4(fmaxf(ma0.x,ma1.x), fmaxf(ma0.y,ma1.y),
                                fmaxf(ma0.z,ma1.z), fmaxf(ma0.w,ma1.w));
        float4 mb = make_float4(fmaxf(mb0.x,mb1.x), fmaxf(mb0.y,mb1.y),
                                fmaxf(mb0.z,mb1.z), fmaxf(mb0.w,mb1.w));
        int s = 0;
#pragma unroll
        for (int j = 0; j < 4; j++) s += (S.offs[j] <= n) ? 1 : 0;
        float4 ga = *(const float4*)&g_segmax[s * 64 + c8];
        float4 gb = *(const float4*)&g_segmax[s * 64 + c8 + 4];
        *(float4*)&gin[r * 192 + c8] = qa;
        *(float4*)&gin[r * 192 + c8 + 4] = qb;
        *(float4*)&gin[r * 192 + 64 + c8] = ma;
        *(float4*)&gin[r * 192 + 64 + c8 + 4] = mb;
        *(float4*)&gin[r * 192 + 128 + c8] = ga;
        *(float4*)&gin[r * 192 + 128 + c8 + 4] = gb;
    }
    int rgrp = t >> 4, hgrp = t & 15;
    float acc[2][4];
#pragma unroll
    for (int a = 0; a < 2; a++)
#pragma unroll
        for (int b = 0; b < 4; b++) acc[a][b] = 0.f;
    for (int i = t; i < 96 * 64; i += 256) sW1h[i] = cgW1[i];
    __syncthreads();
#pragma unroll 4
    for (int j = 0; j < 96; j++) {
        float4 wv = ((const float4*)sW1h)[j * 16 + hgrp];
#pragma unroll
        for (int a = 0; a < 2; a++) {
            float g0 = gin[(rgrp * 2 + a) * 192 + j];
            acc[a][0] += g0 * wv.x; acc[a][1] += g0 * wv.y;
            acc[a][2] += g0 * wv.z; acc[a][3] += g0 * wv.w;
        }
    }
    __syncthreads();
    for (int i = t; i < 96 * 64; i += 256) sW1h[i] = cgW1[96 * 64 + i];
    __syncthreads();
#pragma unroll 4
    for (int j = 0; j < 96; j++) {
        float4 wv = ((const float4*)sW1h)[j * 16 + hgrp];
#pragma unroll
        for (int a = 0; a < 2; a++) {
            float g0 = gin[(rgrp * 2 + a) * 192 + 96 + j];
            acc[a][0] += g0 * wv.x; acc[a][1] += g0 * wv.y;
            acc[a][2] += g0 * wv.z; acc[a][3] += g0 * wv.w;
        }
    }
    __syncthreads();
    float* hs = gin;  // reuse as [32][64]
#pragma unroll
    for (int hi = 0; hi < 4; hi++) {
        int h = hgrp * 4 + hi;
        float sc = S.s_sc[h], sh = S.s_sh[h];
#pragma unroll
        for (int a = 0; a < 2; a++)
            hs[(rgrp * 2 + a) * 64 + h] = fmaxf(acc[a][hi] * sc + sh, 0.f);
    }
    __syncthreads();
    {
        int r = t >> 3, g = t & 7;
        float a0 = S.s_b2[g], a1 = 0.f, a2 = 0.f, a3 = 0.f;
#pragma unroll
        for (int j = 0; j < 64; j += 4) {
            a0 += hs[r * 64 + j]     * sW2[(j)     * 8 + g];
            a1 += hs[r * 64 + j + 1] * sW2[(j + 1) * 8 + g];
            a2 += hs[r * 64 + j + 2] * sW2[(j + 2) * 8 + g];
            a3 += hs[r * 64 + j + 3] * sW2[(j + 3) * 8 + g];
        }
        float a = (a0 + a1) + (a2 + a3);
        g_gate[(n0 + r) * 8 + g] = 1.f / (1.f + __expf(-a));
    }
}

// ---------------- Kernel 4: main, warp-per-point (proven best structure) ----------------
struct alignas(16) MainPerWarp {
    float xe[16 * 29];    // [k][j], reused as hg scratch [16][8]
    float h[16 * 68];     // hidden (swz by kp), then rel (plain)
    float lgt[16 * 8];    // logits -> attn in place
    float sdel[16 * 4];
    float mask[16];
    int   ids[16];
    int   araw[64];
    float cc[12];
};
struct alignas(16) MainSmem {
    float sW1[28 * 64];
    float sW2[64 * 64];
    float sweW1[64 * 8];
    float sweW2[64];
    float pe_sc[64], pe_sh[64], pe_b2[64];
    float we_sc[8], we_sh[8], we_b2[8];
    MainPerWarp w[4];
};

#define WPTS 4   // points per warp

__global__ __launch_bounds__(128, 4) void main_kernel(
    const float* __restrict__ coord, const int* __restrict__ ridx,
    const float* __restrict__ peW1, const float* __restrict__ peb1,
    const float* __restrict__ pebn, const float* __restrict__ peW2,
    const float* __restrict__ peb2,
    const float* __restrict__ weW1, const float* __restrict__ web1,
    const float* __restrict__ webn, const float* __restrict__ weW2,
    const float* __restrict__ web2,
    float* __restrict__ out)
{
    extern __shared__ char smraw[];
    MainSmem& s = *reinterpret_cast<MainSmem*>(smraw);
    int t = threadIdx.x, wid = t >> 5, lane = t & 31;

    for (int i = t; i < 28 * 64; i += 128) s.sW1[i] = peW1[i];
    for (int i = t; i < 64 * 64; i += 128) s.sW2[i] = peW2[i];
    for (int i = t; i < 64 * 8; i += 128) s.sweW1[i] = weW1[i];
    if (t < 64) {
        s.sweW2[t] = weW2[t];
        float sc = pebn[t] * rsqrtf(pebn[192 + t] + EPSB);
        s.pe_sc[t] = sc;
        s.pe_sh[t] = pebn[64 + t] + (peb1[t] - pebn[128 + t]) * sc;
        s.pe_b2[t] = peb2[t];
    }
    if (t < 8) {
        float sc = webn[t] * rsqrtf(webn[24 + t] + EPSB);
        s.we_sc[t] = sc;
        s.we_sh[t] = webn[8 + t] + (web1[t] - webn[16 + t]) * sc;
        s.we_b2[t] = web2[t];
    }
    __syncthreads();

    MainPerWarp& w = s.w[wid];
    int kp = lane >> 3, cq = lane & 7;
    int cbA = cq * 4, cbB = 32 + cq * 4;
    int swz = kp << 2;
    int base = blockIdx.x * (4 * WPTS) + wid * WPTS;

    w.araw[lane]      = ridx[base * KNB + lane];
    w.araw[32 + lane] = ridx[base * KNB + 32 + lane];
    if (lane < 12) w.cc[lane] = coord[base * 3 + lane];
    __syncwarp();

    float ncx = 0.f, ncy = 0.f, ncz = 0.f;
    if (lane < 16) {
        int raw = w.araw[lane];
        int id = raw < 0 ? 0 : raw;
        ncx = coord[id * 3]; ncy = coord[id * 3 + 1]; ncz = coord[id * 3 + 2];
    }

    for (int pp = 0; pp < WPTS; pp++) {
        int n = base + pp;

        if (lane < 16) {
            int raw = w.araw[pp * 16 + lane];
            int id = raw < 0 ? 0 : raw;
            w.ids[lane] = id;
            int sp = raw + 1;
            w.mask[lane] = (sp > 0) ? 1.f : ((sp < 0) ? -1.f : 0.f);
            float dx = ncx - w.cc[pp * 3];
            float dy = ncy - w.cc[pp * 3 + 1];
            float dz = ncz - w.cc[pp * 3 + 2];
            w.sdel[lane * 4] = dx; w.sdel[lane * 4 + 1] = dy; w.sdel[lane * 4 + 2] = dz;
            w.sdel[lane * 4 + 3] = sqrtf(dx * dx + dy * dy + dz * dz);
        }
        __syncwarp();

        // prefetch k-gather (hidden under GEMM1)
        float4 pgk0[4], pgk1[4];
#pragma unroll
        for (int i = 0; i < 4; i++) {
            int id = w.ids[kp * 4 + i];
            pgk0[i] = *(const float4*)&g_k[id * 64 + cbA];
            pgk1[i] = *(const float4*)&g_k[id * 64 + cbB];
        }
        float pgate = 0.f;
        if (lane < 8) pgate = g_gate[n * 8 + lane];

        if (pp + 1 < WPTS && lane < 16) {
            int raw = w.araw[(pp + 1) * 16 + lane];
            int id = raw < 0 ? 0 : raw;
            ncx = coord[id * 3]; ncy = coord[id * 3 + 1]; ncz = coord[id * 3 + 2];
        }

        // xe features
        {
            int k = lane & 15, half = lane >> 4;
            float dx = w.sdel[k * 4], dy = w.sdel[k * 4 + 1];
            float dz = w.sdel[k * 4 + 2], dd = w.sdel[k * 4 + 3];
#pragma unroll
            for (int jj = 0; jj < 14; jj++) {
                int j = half * 14 + jj;
                float v;
                if (j == 0) v = dx;
                else if (j == 1) v = dy;
                else if (j == 2) v = dz;
                else if (j == 3) v = dd;
                else if (j < 20) {
                    int fi = (j - 4) >> 2, r = (j - 4) & 3;
                    float f = (float)(1 << fi) * PI_F;
                    v = (r == 0) ? __sinf(dx * f) : (r == 1) ? __sinf(dy * f)
                      : (r == 2) ? __cosf(dx * f) : __cosf(dy * f);
                } else {
                    int fi = (j - 20) >> 1;
                    float f = (float)(1 << fi) * PI_F;
                    v = ((j - 20) & 1) ? __cosf(dz * f) : __sinf(dz * f);
                }
                w.xe[k * 29 + j] = v;
            }
        }
        __syncwarp();

        // GEMM1: 28 -> 64
        {
            ull acc1[4][4];
#pragma unroll
            for (int i = 0; i < 4; i++)
#pragma unroll
                for (int b = 0; b < 4; b++) acc1[i][b] = 0ULL;
#pragma unroll 4
            for (int j = 0; j < 28; j++) {
                ull xa[4];
#pragma unroll
                for (int i = 0; i < 4; i++) xa[i] = dupf(w.xe[(kp * 4 + i) * 29 + j]);
                longlong2 wA = *(const longlong2*)&s.sW1[j * 64 + cbA];
                longlong2 wB = *(const longlong2*)&s.sW1[j * 64 + cbB];
                ull wb[4] = { (ull)wA.x, (ull)wA.y, (ull)wB.x, (ull)wB.y };
#pragma unroll
                for (int i = 0; i < 4; i++)
#pragma unroll
                    for (int b = 0; b < 4; b++) ffma2(acc1[i][b], xa[i], wb[b]);
            }
            longlong2 scA = *(const longlong2*)&s.pe_sc[cbA];
            longlong2 scB = *(const longlong2*)&s.pe_sc[cbB];
            longlong2 shA = *(const longlong2*)&s.pe_sh[cbA];
            longlong2 shB = *(const longlong2*)&s.pe_sh[cbB];
            ull scp[4] = { (ull)scA.x, (ull)scA.y, (ull)scB.x, (ull)scB.y };
            ull shp[4] = { (ull)shA.x, (ull)shA.y, (ull)shB.x, (ull)shB.y };
#pragma unroll
            for (int i = 0; i < 4; i++) {
                int k = kp * 4 + i;
                float2 r0 = unpk(ffma2_3(acc1[i][0], scp[0], shp[0]));
                float2 r1 = unpk(ffma2_3(acc1[i][1], scp[1], shp[1]));
                float2 r2 = unpk(ffma2_3(acc1[i][2], scp[2], shp[2]));
                float2 r3 = unpk(ffma2_3(acc1[i][3], scp[3], shp[3]));
                float4 lo = make_float4(fmaxf(r0.x, 0.f), fmaxf(r0.y, 0.f),
                                        fmaxf(r1.x, 0.f), fmaxf(r1.y, 0.f));
                float4 hi = make_float4(fmaxf(r2.x, 0.f), fmaxf(r2.y, 0.f),
                                        fmaxf(r3.x, 0.f), fmaxf(r3.y, 0.f));
                *(float4*)&w.h[k * 68 + (cbA ^ swz)] = lo;
                *(float4*)&w.h[k * 68 + (cbB ^ swz)] = hi;
            }
        }
        __syncwarp();

        // GEMM2: 64 -> 64 + relation
        float4 relLo[4], relHi[4];
        {
            float4 qv0 = *(const float4*)&g_q[n * 64 + cbA];
            float4 qv1 = *(const float4*)&g_q[n * 64 + cbB];
            float4 b20 = *(const float4*)&s.pe_b2[cbA];
            float4 b21 = *(const float4*)&s.pe_b2[cbB];
            ull acc2[4][4];
#pragma unroll
            for (int i = 0; i < 4; i++)
#pragma unroll
                for (int b = 0; b < 4; b++) acc2[i][b] = 0ULL;
#pragma unroll 4
            for (int j = 0; j < 64; j++) {
                int jx = j ^ swz;
                ull xa[4];
#pragma unroll
                for (int i = 0; i < 4; i++) xa[i] = dupf(w.h[(kp * 4 + i) * 68 + jx]);
                longlong2 wA = *(const longlong2*)&s.sW2[j * 64 + cbA];
                longlong2 wB = *(const longlong2*)&s.sW2[j * 64 + cbB];
                ull wb[4] = { (ull)wA.x, (ull)wA.y, (ull)wB.x, (ull)wB.y };
#pragma unroll
                for (int i = 0; i < 4; i++)
#pragma unroll
                    for (int b = 0; b < 4; b++) ffma2(acc2[i][b], xa[i], wb[b]);
            }
#pragma unroll
            for (int i = 0; i < 4; i++) {
                float2 p0 = unpk(acc2[i][0]);
                float2 p1 = unpk(acc2[i][1]);
                float2 p2 = unpk(acc2[i][2]);
                float2 p3 = unpk(acc2[i][3]);
                relLo[i] = make_float4(pgk0[i].x - qv0.x + p0.x + b20.x,
                                       pgk0[i].y - qv0.y + p0.y + b20.y,
                                       pgk0[i].z - qv0.z + p1.x + b20.z,
                                       pgk0[i].w - qv0.w + p1.y + b20.w);
                relHi[i] = make_float4(pgk1[i].x - qv1.x + p2.x + b21.x,
                                       pgk1[i].y - qv1.y + p2.y + b21.y,
                                       pgk1[i].z - qv1.z + p3.x + b21.z,
                                       pgk1[i].w - qv1.w + p3.y + b21.w);
            }
        }
        __syncwarp();
#pragma unroll
        for (int i = 0; i < 4; i++) {
            int k = kp * 4 + i;
            *(float4*)&w.h[k * 68 + cbA] = relLo[i];   // plain layout
            *(float4*)&w.h[k * 68 + cbB] = relHi[i];
        }
        __syncwarp();

        // prefetch v-gather (hidden under geom+softmax)
        float2 pv[16];
        {
            int c0 = lane * 2;
#pragma unroll
            for (int k = 0; k < 16; k++)
                pv[k] = *(const float2*)&g_v[w.ids[k] * 64 + c0];
        }

        // geom hidden: 64 -> 8
        int k2 = lane >> 1, gq = (lane & 1) * 4;
        {
            float a0 = 0.f, a1 = 0.f, a2 = 0.f, a3 = 0.f;
#pragma unroll 8
            for (int c = 0; c < 64; c++) {
                float r = w.h[k2 * 68 + c];
                float4 wv = *(const float4*)&s.sweW1[c * 8 + gq];
                a0 += r * wv.x; a1 += r * wv.y; a2 += r * wv.z; a3 += r * wv.w;
            }
            float* hg = w.xe;  // scratch [16][8]
            hg[k2 * 8 + gq]     = fmaxf(a0 * s.we_sc[gq]     + s.we_sh[gq], 0.f);
            hg[k2 * 8 + gq + 1] = fmaxf(a1 * s.we_sc[gq + 1] + s.we_sh[gq + 1], 0.f);
            hg[k2 * 8 + gq + 2] = fmaxf(a2 * s.we_sc[gq + 2] + s.we_sh[gq + 2], 0.f);
            hg[k2 * 8 + gq + 3] = fmaxf(a3 * s.we_sc[gq + 3] + s.we_sh[gq + 3], 0.f);
        }
        __syncwarp();

        // geom out: 8 -> 8
        {
            const float* hg = w.xe;
            float a0 = s.we_b2[gq], a1 = s.we_b2[gq + 1];
            float a2 = s.we_b2[gq + 2], a3 = s.we_b2[gq + 3];
#pragma unroll
            for (int j = 0; j < 8; j++) {
                float hv = hg[k2 * 8 + j];
                float4 wv = *(const float4*)&s.sweW2[j * 8 + gq];
                a0 += hv * wv.x; a1 += hv * wv.y; a2 += hv * wv.z; a3 += hv * wv.w;
            }
            w.lgt[k2 * 8 + gq] = a0; w.lgt[k2 * 8 + gq + 1] = a1;
            w.lgt[k2 * 8 + gq + 2] = a2; w.lgt[k2 * 8 + gq + 3] = a3;
        }
        __syncwarp();

        // softmax
        if (lane < 8) {
            float m = -1e30f;
            float l[16];
#pragma unroll
            for (int k = 0; k < 16; k++) { l[k] = w.lgt[k * 8 + lane] * pgate; m = fmaxf(m, l[k]); }
            float ssum = 0.f;
#pragma unroll
            for (int k = 0; k < 16; k++) { l[k] = __expf(l[k] - m); ssum += l[k]; }
            float inv = 1.f / ssum;
#pragma unroll
            for (int k = 0; k < 16; k++) w.lgt[k * 8 + lane] = l[k] * inv * w.mask[k];
        }
        __syncwarp();

        // output
        {
            int c0 = lane * 2, gidx = lane >> 2;
            float ox = 0.f, oy = 0.f;
#pragma unroll
            for (int k = 0; k < 16; k++) {
                float a = w.lgt[k * 8 + gidx];
                ox += pv[k].x * a; oy += pv[k].y * a;
            }
            *(float2*)&out[n * 64 + c0] = make_float2(ox, oy);
        }
        __syncwarp();
    }
}

extern "C" void kernel_launch(void* const* d_in, const int* in_sizes, int n_in,
                              void* d_out, int out_size) {
    const float* feat   = (const float*)d_in[0];
    const float* coord  = (const float*)d_in[1];
    const int*   ridx   = (const int*)d_in[2];
    const int*   offset = (const int*)d_in[3];
    const float* Wq = (const float*)d_in[4];
    const float* bq = (const float*)d_in[5];
    const float* bnq = (const float*)d_in[6];
    const float* Wk = (const float*)d_in[7];
    const float* bk = (const float*)d_in[8];
    const float* bnk = (const float*)d_in[9];
    const float* Wv = (const float*)d_in[10];
    const float* bv = (const float*)d_in[11];
    const float* peW1 = (const float*)d_in[12];
    const float* peb1 = (const float*)d_in[13];
    const float* pebn = (const float*)d_in[14];
    const float* peW2 = (const float*)d_in[15];
    const float* peb2 = (const float*)d_in[16];
    const float* weW1 = (const float*)d_in[17];
    const float* web1 = (const float*)d_in[18];
    const float* webn = (const float*)d_in[19];
    const float* weW2 = (const float*)d_in[20];
    const float* web2 = (const float*)d_in[21];
    const float* cgW1 = (const float*)d_in[22];
    const float* cgb1 = (const float*)d_in[23];
    const float* cgbn = (const float*)d_in[24];
    const float* cgW2 = (const float*)d_in[25];
    const float* cgb2 = (const float*)d_in[26];
    float* out = (float*)d_out;

    static int smem_set = 0;
    size_t shmem_main = sizeof(MainSmem);
    size_t shmem_gate = sizeof(GateSmem);
    if (!smem_set) {
        cudaFuncSetAttribute(main_kernel, cudaFuncAttributeMaxDynamicSharedMemorySize, (int)shmem_main);
        cudaFuncSetAttribute(gate_kernel, cudaFuncAttributeMaxDynamicSharedMemorySize, (int)shmem_gate);
        smem_set = 1;
    }

    segmax_init_kernel<<<1, 256>>>();
    qkv_kernel<<<NPTS / 64, 256>>>(feat, Wq, bq, bnq, Wk, bk, bnk, Wv, bv, offset);
    gate_kernel<<<NPTS / 32, 256, shmem_gate>>>(ridx, offset, cgW1, cgb1, cgbn, cgW2, cgb2);
    main_kernel<<<NPTS / (4 * WPTS), 128, shmem_main>>>(coord, ridx, peW1, peb1, pebn, peW2, peb2,
                                                        weW1, web1, webn, weW2, web2, out);
}

// round 16
// speedup vs baseline: 1.0787x; 1.0787x over previous
#include <cuda_runtime.h>
#include <cuda_bf16.h>
#include <math.h>

#define NPTS 65536
#define KNB  16
#define EPSB 1e-5f
#define PI_F 3.14159265358979f

typedef unsigned long long ull;

__device__ float g_q[NPTS * 64];
__device__ float g_k[NPTS * 64];
__device__ float g_v[NPTS * 64];
__device__ float g_gate[NPTS * 8];
__device__ float g_segmax[4 * 64];

// ---- packed f32x2 helpers ----
__device__ __forceinline__ void ffma2(ull& d, ull a, ull b) {
    asm("fma.rn.f32x2 %0, %1, %2, %0;" : "+l"(d) : "l"(a), "l"(b));
}
__device__ __forceinline__ ull ffma2_3(ull a, ull b, ull c) {
    ull d; asm("fma.rn.f32x2 %0, %1, %2, %3;" : "=l"(d) : "l"(a), "l"(b), "l"(c)); return d;
}
__device__ __forceinline__ ull dupf(float x) {
    ull r; asm("mov.b64 %0, {%1, %1};" : "=l"(r) : "f"(x)); return r;
}
__device__ __forceinline__ float2 unpk(ull v) {
    float2 r; asm("mov.b64 {%0, %1}, %2;" : "=f"(r.x), "=f"(r.y) : "l"(v)); return r;
}

// ---------------- Kernel 1: fused q,k,v projections (R13 proven) ----------------
__global__ __launch_bounds__(256) void qkv_kernel(
    const float* __restrict__ feat,
    const float* __restrict__ Wq, const float* __restrict__ bq, const float* __restrict__ bnq,
    const float* __restrict__ Wk, const float* __restrict__ bk, const float* __restrict__ bnk,
    const float* __restrict__ Wv, const float* __restrict__ bv)
{
    __shared__ float sf[64 * 64];
    int t = threadIdx.x;
    int row0 = blockIdx.x * 64;
    for (int i = t; i < 64 * 64; i += 256) sf[i] = feat[row0 * 64 + i];
    __syncthreads();
    int c = t & 63, rg = t >> 6;
    float aq[16], ak[16], av[16];
#pragma unroll
    for (int r = 0; r < 16; r++) { aq[r] = 0.f; ak[r] = 0.f; av[r] = 0.f; }
#pragma unroll 4
    for (int j = 0; j < 64; j++) {
        float wq = Wq[j * 64 + c], wk = Wk[j * 64 + c], wv = Wv[j * 64 + c];
        const float* fr = &sf[(rg * 16) * 64 + j];
#pragma unroll
        for (int r = 0; r < 16; r++) {
            float f = fr[r * 64];
            aq[r] += f * wq; ak[r] += f * wk; av[r] += f * wv;
        }
    }
    float sq  = bnq[c] * rsqrtf(bnq[192 + c] + EPSB);
    float shq = bnq[64 + c] + (bq[c] - bnq[128 + c]) * sq;
    float sk  = bnk[c] * rsqrtf(bnk[192 + c] + EPSB);
    float shk = bnk[64 + c] + (bk[c] - bnk[128 + c]) * sk;
    float bvc = bv[c];
#pragma unroll
    for (int r = 0; r < 16; r++) {
        int row = row0 + rg * 16 + r;
        g_q[row * 64 + c] = fmaxf(aq[r] * sq + shq, 0.f);
        g_k[row * 64 + c] = fmaxf(ak[r] * sk + shk, 0.f);
        g_v[row * 64 + c] = av[r] + bvc;
    }
}

// ---------------- Kernel 2: segment max of q (q >= 0) ----------------
__global__ void segmax_init_kernel() { g_segmax[threadIdx.x] = 0.f; }

__global__ __launch_bounds__(256) void segmax_kernel() {
    __shared__ float part[4 * 64];
    int t = threadIdx.x, c = t & 63, rs = t >> 6;
    int base = blockIdx.x * 1024 + rs * 256;
    float m = 0.f;
    for (int i = 0; i < 256; i++) m = fmaxf(m, g_q[(base + i) * 64 + c]);
    part[rs * 64 + c] = m;
    __syncthreads();
    if (rs == 0) {
        float mm = fmaxf(fmaxf(part[c], part[64 + c]), fmaxf(part[128 + c], part[192 + c]));
        int seg = (blockIdx.x * 1024) / (NPTS / 4);
        atomicMax((int*)&g_segmax[seg * 64 + c], __float_as_int(mm));
    }
}

// ---------------- Kernel 3: gate MLP, 32 rows per block, 256 threads ----------------
struct alignas(16) GateSmem {
    float sW1h[96 * 64];
    float gin[32 * 192];
    float sW2[64 * 8];
    float s_sc[64], s_sh[64], s_b2[8];
    int   offs[4];
    int   sidx[32 * 16];
};

__global__ __launch_bounds__(256, 4) void gate_kernel(
    const int* __restrict__ ridx, const int* __restrict__ offset,
    const float* __restrict__ cgW1, const float* __restrict__ cgb1,
    const float* __restrict__ cgbn, const float* __restrict__ cgW2,
    const float* __restrict__ cgb2)
{
    extern __shared__ char graw[];
    GateSmem& S = *reinterpret_cast<GateSmem*>(graw);
    float* sW1h = S.sW1h;
    float* gin  = S.gin;
    float* sW2  = S.sW2;
    int t = threadIdx.x;
    int n0 = blockIdx.x * 32;
    for (int i = t; i < 64 * 8; i += 256) sW2[i] = cgW2[i];
    if (t < 64) {
        float sc = cgbn[t] * rsqrtf(cgbn[192 + t] + EPSB);
        S.s_sc[t] = sc;
        S.s_sh[t] = cgbn[64 + t] + (cgb1[t] - cgbn[128 + t]) * sc;
    }
    if (t < 8) S.s_b2[t] = cgb2[t];
    if (t < 4) S.offs[t] = offset[t];
    for (int i = t; i < 512; i += 256) {
        int raw = ridx[n0 * KNB + i];
        S.sidx[i] = raw < 0 ? 0 : raw;
    }
    __syncthreads();
    {
        int c8 = (t & 7) * 8;
        int r = t >> 3;
        int n = n0 + r;
        float4 qa = *(const float4*)&g_q[n * 64 + c8];
        float4 qb = *(const float4*)&g_q[n * 64 + c8 + 4];
        float4 ma0 = make_float4(0.f,0.f,0.f,0.f), ma1 = ma0;
        float4 mb0 = ma0, mb1 = ma0;
#pragma unroll
        for (int k = 0; k < KNB; k += 2) {
            int id0 = S.sidx[r * KNB + k];
            int id1 = S.sidx[r * KNB + k + 1];
            float4 va0 = *(const float4*)&g_q[id0 * 64 + c8];
            float4 vb0 = *(const float4*)&g_q[id0 * 64 + c8 + 4];
            float4 va1 = *(const float4*)&g_q[id1 * 64 + c8];
            float4 vb1 = *(const float4*)&g_q[id1 * 64 + c8 + 4];
            ma0.x = fmaxf(ma0.x, va0.x); ma0.y = fmaxf(ma0.y, va0.y);
            ma0.z = fmaxf(ma0.z, va0.z); ma0.w = fmaxf(ma0.w, va0.w);
            mb0.x = fmaxf(mb0.x, vb0.x); mb0.y = fmaxf(mb0.y, vb0.y);
            mb0.z = fmaxf(mb0.z, vb0.z); mb0.w = fmaxf(mb0.w, vb0.w);
            ma1.x = fmaxf(ma1.x, va1.x); ma1.y = fmaxf(ma1.y, va1.y);
            ma1.z = fmaxf(ma1.z, va1.z); ma1.w = fmaxf(ma1.w, va1.w);
            mb1.x = fmaxf(mb1.x, vb1.x); mb1.y = fmaxf(mb1.y, vb1.y);
            mb1.z = fmaxf(mb1.z, vb1.z); mb1.w = fmaxf(mb1.w, vb1.w);
        }
        float4 ma = make_float4(fmaxf(ma0.x,ma1.x), fmaxf(ma0.y,ma1.y),
                                fmaxf(ma0.z,ma1.z), fmaxf(ma0.w,ma1.w));
        float4 mb = make_float4(fmaxf(mb0.x,mb1.x), fmaxf(mb0.y,mb1.y),
                                fmaxf(mb0.z,mb1.z), fmaxf(mb0.w,mb1.w));
        int s = 0;
#pragma unroll
        for (int j = 0; j < 4; j++) s += (S.offs[j] <= n) ? 1 : 0;
        float4 ga = *(const float4*)&g_segmax[s * 64 + c8];
        float4 gb = *(const float4*)&g_segmax[s * 64 + c8 + 4];
        *(float4*)&gin[r * 192 + c8] = qa;
        *(float4*)&gin[r * 192 + c8 + 4] = qb;
        *(float4*)&gin[r * 192 + 64 + c8] = ma;
        *(float4*)&gin[r * 192 + 64 + c8 + 4] = mb;
        *(float4*)&gin[r * 192 + 128 + c8] = ga;
        *(float4*)&gin[r * 192 + 128 + c8 + 4] = gb;
    }
    int rgrp = t >> 4, hgrp = t & 15;
    float acc[2][4];
#pragma unroll
    for (int a = 0; a < 2; a++)
#pragma unroll
        for (int b = 0; b < 4; b++) acc[a][b] = 0.f;
    for (int i = t; i < 96 * 64; i += 256) sW1h[i] = cgW1[i];
    __syncthreads();
#pragma unroll 4
    for (int j = 0; j < 96; j++) {
        float4 wv = ((const float4*)sW1h)[j * 16 + hgrp];
#pragma unroll
        for (int a = 0; a < 2; a++) {
            float g0 = gin[(rgrp * 2 + a) * 192 + j];
            acc[a][0] += g0 * wv.x; acc[a][1] += g0 * wv.y;
            acc[a][2] += g0 * wv.z; acc[a][3] += g0 * wv.w;
        }
    }
    __syncthreads();
    for (int i = t; i < 96 * 64; i += 256) sW1h[i] = cgW1[96 * 64 + i];
    __syncthreads();
#pragma unroll 4
    for (int j = 0; j < 96; j++) {
        float4 wv = ((const float4*)sW1h)[j * 16 + hgrp];
#pragma unroll
        for (int a = 0; a < 2; a++) {
            float g0 = gin[(rgrp * 2 + a) * 192 + 96 + j];
            acc[a][0] += g0 * wv.x; acc[a][1] += g0 * wv.y;
            acc[a][2] += g0 * wv.z; acc[a][3] += g0 * wv.w;
        }
    }
    __syncthreads();
    float* hs = gin;  // reuse as [32][64]
#pragma unroll
    for (int hi = 0; hi < 4; hi++) {
        int h = hgrp * 4 + hi;
        float sc = S.s_sc[h], sh = S.s_sh[h];
#pragma unroll
        for (int a = 0; a < 2; a++)
            hs[(rgrp * 2 + a) * 64 + h] = fmaxf(acc[a][hi] * sc + sh, 0.f);
    }
    __syncthreads();
    {
        int r = t >> 3, g = t & 7;
        float a0 = S.s_b2[g], a1 = 0.f, a2 = 0.f, a3 = 0.f;
#pragma unroll
        for (int j = 0; j < 64; j += 4) {
            a0 += hs[r * 64 + j]     * sW2[(j)     * 8 + g];
            a1 += hs[r * 64 + j + 1] * sW2[(j + 1) * 8 + g];
            a2 += hs[r * 64 + j + 2] * sW2[(j + 2) * 8 + g];
            a3 += hs[r * 64 + j + 3] * sW2[(j + 3) * 8 + g];
        }
        float a = (a0 + a1) + (a2 + a3);
        g_gate[(n0 + r) * 8 + g] = 1.f / (1.f + __expf(-a));
    }
}

// ---------------- Kernel 4: main, warp-per-point + paired LDS.64 x-loads ----------------
// xe stride 30 (even) so j-pairs are 8B-aligned; h stride 68 even likewise.
struct alignas(16) MainPerWarp {
    float xe[16 * 30];    // [k][j] stride 30, reused as hg scratch [16][8]
    float h[16 * 68];     // hidden (swz by kp), then rel (plain)
    float lgt[16 * 8];    // logits -> attn in place
    float sdel[16 * 4];
    float mask[16];
    int   ids[16];
    int   araw[64];
    float cc[12];
};
struct alignas(16) MainSmem {
    float sW1[28 * 64];
    float sW2[64 * 64];
    float sweW1[64 * 8];
    float sweW2[64];
    float pe_sc[64], pe_sh[64], pe_b2[64];
    float we_sc[8], we_sh[8], we_b2[8];
    MainPerWarp w[4];
};

#define WPTS 4   // points per warp

__global__ __launch_bounds__(128, 4) void main_kernel(
    const float* __restrict__ coord, const int* __restrict__ ridx,
    const float* __restrict__ peW1, const float* __restrict__ peb1,
    const float* __restrict__ pebn, const float* __restrict__ peW2,
    const float* __restrict__ peb2,
    const float* __restrict__ weW1, const float* __restrict__ web1,
    const float* __restrict__ webn, const float* __restrict__ weW2,
    const float* __restrict__ web2,
    float* __restrict__ out)
{
    extern __shared__ char smraw[];
    MainSmem& s = *reinterpret_cast<MainSmem*>(smraw);
    int t = threadIdx.x, wid = t >> 5, lane = t & 31;

    for (int i = t; i < 28 * 64; i += 128) s.sW1[i] = peW1[i];
    for (int i = t; i < 64 * 64; i += 128) s.sW2[i] = peW2[i];
    for (int i = t; i < 64 * 8; i += 128) s.sweW1[i] = weW1[i];
    if (t < 64) {
        s.sweW2[t] = weW2[t];
        float sc = pebn[t] * rsqrtf(pebn[192 + t] + EPSB);
        s.pe_sc[t] = sc;
        s.pe_sh[t] = pebn[64 + t] + (peb1[t] - pebn[128 + t]) * sc;
        s.pe_b2[t] = peb2[t];
    }
    if (t < 8) {
        float sc = webn[t] * rsqrtf(webn[24 + t] + EPSB);
        s.we_sc[t] = sc;
        s.we_sh[t] = webn[8 + t] + (web1[t] - webn[16 + t]) * sc;
        s.we_b2[t] = web2[t];
    }
    __syncthreads();

    MainPerWarp& w = s.w[wid];
    int kp = lane >> 3, cq = lane & 7;
    int cbA = cq * 4, cbB = 32 + cq * 4;
    int swz = kp << 2;
    int base = blockIdx.x * (4 * WPTS) + wid * WPTS;

    w.araw[lane]      = ridx[base * KNB + lane];
    w.araw[32 + lane] = ridx[base * KNB + 32 + lane];
    if (lane < 12) w.cc[lane] = coord[base * 3 + lane];
    __syncwarp();

    float ncx = 0.f, ncy = 0.f, ncz = 0.f;
    if (lane < 16) {
        int raw = w.araw[lane];
        int id = raw < 0 ? 0 : raw;
        ncx = coord[id * 3]; ncy = coord[id * 3 + 1]; ncz = coord[id * 3 + 2];
    }

    for (int pp = 0; pp < WPTS; pp++) {
        int n = base + pp;

        if (lane < 16) {
            int raw = w.araw[pp * 16 + lane];
            int id = raw < 0 ? 0 : raw;
            w.ids[lane] = id;
            int sp = raw + 1;
            w.mask[lane] = (sp > 0) ? 1.f : ((sp < 0) ? -1.f : 0.f);
            float dx = ncx - w.cc[pp * 3];
            float dy = ncy - w.cc[pp * 3 + 1];
            float dz = ncz - w.cc[pp * 3 + 2];
            w.sdel[lane * 4] = dx; w.sdel[lane * 4 + 1] = dy; w.sdel[lane * 4 + 2] = dz;
            w.sdel[lane * 4 + 3] = sqrtf(dx * dx + dy * dy + dz * dz);
        }
        __syncwarp();

        // prefetch k-gather (hidden under GEMM1)
        float4 pgk0[4], pgk1[4];
#pragma unroll
        for (int i = 0; i < 4; i++) {
            int id = w.ids[kp * 4 + i];
            pgk0[i] = *(const float4*)&g_k[id * 64 + cbA];
            pgk1[i] = *(const float4*)&g_k[id * 64 + cbB];
        }
        float pgate = 0.f;
        if (lane < 8) pgate = g_gate[n * 8 + lane];

        if (pp + 1 < WPTS && lane < 16) {
            int raw = w.araw[(pp + 1) * 16 + lane];
            int id = raw < 0 ? 0 : raw;
            ncx = coord[id * 3]; ncy = coord[id * 3 + 1]; ncz = coord[id * 3 + 2];
        }

        // xe features (stride 30)
        {
            int k = lane & 15, half = lane >> 4;
            float dx = w.sdel[k * 4], dy = w.sdel[k * 4 + 1];
            float dz = w.sdel[k * 4 + 2], dd = w.sdel[k * 4 + 3];
#pragma unroll
            for (int jj = 0; jj < 14; jj++) {
                int j = half * 14 + jj;
                float v;
                if (j == 0) v = dx;
                else if (j == 1) v = dy;
                else if (j == 2) v = dz;
                else if (j == 3) v = dd;
                else if (j < 20) {
                    int fi = (j - 4) >> 2, r = (j - 4) & 3;
                    float f = (float)(1 << fi) * PI_F;
                    v = (r == 0) ? __sinf(dx * f) : (r == 1) ? __sinf(dy * f)
                      : (r == 2) ? __cosf(dx * f) : __cosf(dy * f);
                } else {
                    int fi = (j - 20) >> 1;
                    float f = (float)(1 << fi) * PI_F;
                    v = ((j - 20) & 1) ? __cosf(dz * f) : __sinf(dz * f);
                }
                w.xe[k * 30 + j] = v;
            }
        }
        __syncwarp();

        // GEMM1: 28 -> 64, paired LDS.64 x-loads (j step 2)
        {
            ull acc1[4][4];
#pragma unroll
            for (int i = 0; i < 4; i++)
#pragma unroll
                for (int b = 0; b < 4; b++) acc1[i][b] = 0ULL;
#pragma unroll 2
            for (int j = 0; j < 28; j += 2) {
                float2 xv[4];
#pragma unroll
                for (int i = 0; i < 4; i++)
                    xv[i] = *(const float2*)&w.xe[(kp * 4 + i) * 30 + j];
                longlong2 wA0 = *(const longlong2*)&s.sW1[j * 64 + cbA];
                longlong2 wB0 = *(const longlong2*)&s.sW1[j * 64 + cbB];
                longlong2 wA1 = *(const longlong2*)&s.sW1[(j + 1) * 64 + cbA];
                longlong2 wB1 = *(const longlong2*)&s.sW1[(j + 1) * 64 + cbB];
                ull wb0[4] = { (ull)wA0.x, (ull)wA0.y, (ull)wB0.x, (ull)wB0.y };
                ull wb1[4] = { (ull)wA1.x, (ull)wA1.y, (ull)wB1.x, (ull)wB1.y };
#pragma unroll
                for (int i = 0; i < 4; i++) {
                    ull xe0 = dupf(xv[i].x), xe1 = dupf(xv[i].y);
#pragma unroll
                    for (int b = 0; b < 4; b++) {
                        ffma2(acc1[i][b], xe0, wb0[b]);
                        ffma2(acc1[i][b], xe1, wb1[b]);
                    }
                }
            }
            longlong2 scA = *(const longlong2*)&s.pe_sc[cbA];
            longlong2 scB = *(const longlong2*)&s.pe_sc[cbB];
            longlong2 shA = *(const longlong2*)&s.pe_sh[cbA];
            longlong2 shB = *(const longlong2*)&s.pe_sh[cbB];
            ull scp[4] = { (ull)scA.x, (ull)scA.y, (ull)scB.x, (ull)scB.y };
            ull shp[4] = { (ull)shA.x, (ull)shA.y, (ull)shB.x, (ull)shB.y };
#pragma unroll
            for (int i = 0; i < 4; i++) {
                int k = kp * 4 + i;
                float2 r0 = unpk(ffma2_3(acc1[i][0], scp[0], shp[0]));
                float2 r1 = unpk(ffma2_3(acc1[i][1], scp[1], shp[1]));
                float2 r2 = unpk(ffma2_3(acc1[i][2], scp[2], shp[2]));
                float2 r3 = unpk(ffma2_3(acc1[i][3], scp[3], shp[3]));
                float4 lo = make_float4(fmaxf(r0.x, 0.f), fmaxf(r0.y, 0.f),
                                        fmaxf(r1.x, 0.f), fmaxf(r1.y, 0.f));
                float4 hi = make_float4(fmaxf(r2.x, 0.f), fmaxf(r2.y, 0.f),
                                        fmaxf(r3.x, 0.f), fmaxf(r3.y, 0.f));
                *(float4*)&w.h[k * 68 + (cbA ^ swz)] = lo;
                *(float4*)&w.h[k * 68 + (cbB ^ swz)] = hi;
            }
        }
        __syncwarp();

        // GEMM2: 64 -> 64 + relation, paired LDS.64 x-loads
        float4 relLo[4], relHi[4];
        {
            float4 qv0 = *(const float4*)&g_q[n * 64 + cbA];
            float4 qv1 = *(const float4*)&g_q[n * 64 + cbB];
            float4 b20 = *(const float4*)&s.pe_b2[cbA];
            float4 b21 = *(const float4*)&s.pe_b2[cbB];
            ull acc2[4][4];
#pragma unroll
            for (int i = 0; i < 4; i++)
#pragma unroll
                for (int b = 0; b < 4; b++) acc2[i][b] = 0ULL;
#pragma unroll 2
            for (int j = 0; j < 64; j += 2) {
                int jx = j ^ swz;   // swz multiple of 4 -> jx, jx+1 consecutive, 8B aligned
                float2 xv[4];
#pragma unroll
                for (int i = 0; i < 4; i++)
                    xv[i] = *(const float2*)&w.h[(kp * 4 + i) * 68 + jx];
                longlong2 wA0 = *(const longlong2*)&s.sW2[j * 64 + cbA];
                longlong2 wB0 = *(const longlong2*)&s.sW2[j * 64 + cbB];
                longlong2 wA1 = *(const longlong2*)&s.sW2[(j + 1) * 64 + cbA];
                longlong2 wB1 = *(const longlong2*)&s.sW2[(j + 1) * 64 + cbB];
                ull wb0[4] = { (ull)wA0.x, (ull)wA0.y, (ull)wB0.x, (ull)wB0.y };
                ull wb1[4] = { (ull)wA1.x, (ull)wA1.y, (ull)wB1.x, (ull)wB1.y };
#pragma unroll
                for (int i = 0; i < 4; i++) {
                    ull xe0 = dupf(xv[i].x), xe1 = dupf(xv[i].y);
#pragma unroll
                    for (int b = 0; b < 4; b++) {
                        ffma2(acc2[i][b], xe0, wb0[b]);
                        ffma2(acc2[i][b], xe1, wb1[b]);
                    }
                }
            }
#pragma unroll
            for (int i = 0; i < 4; i++) {
                float2 p0 = unpk(acc2[i][0]);
                float2 p1 = unpk(acc2[i][1]);
                float2 p2 = unpk(acc2[i][2]);
                float2 p3 = unpk(acc2[i][3]);
                relLo[i] = make_float4(pgk0[i].x - qv0.x + p0.x + b20.x,
                                       pgk0[i].y - qv0.y + p0.y + b20.y,
                                       pgk0[i].z - qv0.z + p1.x + b20.z,
                                       pgk0[i].w - qv0.w + p1.y + b20.w);
                relHi[i] = make_float4(pgk1[i].x - qv1.x + p2.x + b21.x,
                                       pgk1[i].y - qv1.y + p2.y + b21.y,
                                       pgk1[i].z - qv1.z + p3.x + b21.z,
                                       pgk1[i].w - qv1.w + p3.y + b21.w);
            }
        }
        __syncwarp();
#pragma unroll
        for (int i = 0; i < 4; i++) {
            int k = kp * 4 + i;
            *(float4*)&w.h[k * 68 + cbA] = relLo[i];   // plain layout
            *(float4*)&w.h[k * 68 + cbB] = relHi[i];
        }
        __syncwarp();

        // prefetch v-gather (hidden under geom+softmax)
        float2 pv[16];
        {
            int c0 = lane * 2;
#pragma unroll
            for (int k = 0; k < 16; k++)
                pv[k] = *(const float2*)&g_v[w.ids[k] * 64 + c0];
        }

        // geom hidden: 64 -> 8
        int k2 = lane >> 1, gq = (lane & 1) * 4;
        {
            float a0 = 0.f, a1 = 0.f, a2 = 0.f, a3 = 0.f;
#pragma unroll 8
            for (int c = 0; c < 64; c++) {
                float r = w.h[k2 * 68 + c];
                float4 wv = *(const float4*)&s.sweW1[c * 8 + gq];
                a0 += r * wv.x; a1 += r * wv.y; a2 += r * wv.z; a3 += r * wv.w;
            }
            float* hg = w.xe;  // scratch [16][8]
            hg[k2 * 8 + gq]     = fmaxf(a0 * s.we_sc[gq]     + s.we_sh[gq], 0.f);
            hg[k2 * 8 + gq + 1] = fmaxf(a1 * s.we_sc[gq + 1] + s.we_sh[gq + 1], 0.f);
            hg[k2 * 8 + gq + 2] = fmaxf(a2 * s.we_sc[gq + 2] + s.we_sh[gq + 2], 0.f);
            hg[k2 * 8 + gq + 3] = fmaxf(a3 * s.we_sc[gq + 3] + s.we_sh[gq + 3], 0.f);
        }
        __syncwarp();

        // geom out: 8 -> 8
        {
            const float* hg = w.xe;
            float a0 = s.we_b2[gq], a1 = s.we_b2[gq + 1];
            float a2 = s.we_b2[gq + 2], a3 = s.we_b2[gq + 3];
#pragma unroll
            for (int j = 0; j < 8; j++) {
                float hv = hg[k2 * 8 + j];
                float4 wv = *(const float4*)&s.sweW2[j * 8 + gq];
                a0 += hv * wv.x; a1 += hv * wv.y; a2 += hv * wv.z; a3 += hv * wv.w;
            }
            w.lgt[k2 * 8 + gq] = a0; w.lgt[k2 * 8 + gq + 1] = a1;
            w.lgt[k2 * 8 + gq + 2] = a2; w.lgt[k2 * 8 + gq + 3] = a3;
        }
        __syncwarp();

        // softmax
        if (lane < 8) {
            float m = -1e30f;
            float l[16];
#pragma unroll
            for (int k = 0; k < 16; k++) { l[k] = w.lgt[k * 8 + lane] * pgate; m = fmaxf(m, l[k]); }
            float ssum = 0.f;
#pragma unroll
            for (int k = 0; k < 16; k++) { l[k] = __expf(l[k] - m); ssum += l[k]; }
            float inv = 1.f / ssum;
#pragma unroll
            for (int k = 0; k < 16; k++) w.lgt[k * 8 + lane] = l[k] * inv * w.mask[k];
        }
        __syncwarp();

        // output
        {
            int c0 = lane * 2, gidx = lane >> 2;
            float ox = 0.f, oy = 0.f;
#pragma unroll
            for (int k = 0; k < 16; k++) {
                float a = w.lgt[k * 8 + gidx];
                ox += pv[k].x * a; oy += pv[k].y * a;
            }
            *(float2*)&out[n * 64 + c0] = make_float2(ox, oy);
        }
        __syncwarp();
    }
}

extern "C" void kernel_launch(void* const* d_in, const int* in_sizes, int n_in,
                              void* d_out, int out_size) {
    const float* feat   = (const float*)d_in[0];
    const float* coord  = (const float*)d_in[1];
    const int*   ridx   = (const int*)d_in[2];
    const int*   offset = (const int*)d_in[3];
    const float* Wq = (const float*)d_in[4];
    const float* bq = (const float*)d_in[5];
    const float* bnq = (const float*)d_in[6];
    const float* Wk = (const float*)d_in[7];
    const float* bk = (const float*)d_in[8];
    const float* bnk = (const float*)d_in[9];
    const float* Wv = (const float*)d_in[10];
    const float* bv = (const float*)d_in[11];
    const float* peW1 = (const float*)d_in[12];
    const float* peb1 = (const float*)d_in[13];
    const float* pebn = (const float*)d_in[14];
    const float* peW2 = (const float*)d_in[15];
    const float* peb2 = (const float*)d_in[16];
    const float* weW1 = (const float*)d_in[17];
    const float* web1 = (const float*)d_in[18];
    const float* webn = (const float*)d_in[19];
    const float* weW2 = (const float*)d_in[20];
    const float* web2 = (const float*)d_in[21];
    const float* cgW1 = (const float*)d_in[22];
    const float* cgb1 = (const float*)d_in[23];
    const float* cgbn = (const float*)d_in[24];
    const float* cgW2 = (const float*)d_in[25];
    const float* cgb2 = (const float*)d_in[26];
    float* out = (float*)d_out;

    static int smem_set = 0;
    size_t shmem_main = sizeof(MainSmem);
    size_t shmem_gate = sizeof(GateSmem);
    if (!smem_set) {
        cudaFuncSetAttribute(main_kernel, cudaFuncAttributeMaxDynamicSharedMemorySize, (int)shmem_main);
        cudaFuncSetAttribute(gate_kernel, cudaFuncAttributeMaxDynamicSharedMemorySize, (int)shmem_gate);
        smem_set = 1;
    }

    qkv_kernel<<<NPTS / 64, 256>>>(feat, Wq, bq, bnq, Wk, bk, bnk, Wv, bv);
    segmax_init_kernel<<<1, 256>>>();
    segmax_kernel<<<NPTS / 1024, 256>>>();
    gate_kernel<<<NPTS / 32, 256, shmem_gate>>>(ridx, offset, cgW1, cgb1, cgbn, cgW2, cgb2);
    main_kernel<<<NPTS / (4 * WPTS), 128, shmem_main>>>(coord, ridx, peW1, peb1, pebn, peW2, peb2,
                                                        weW1, web1, webn, weW2, web2, out);
}